// round 6
// baseline (speedup 1.0000x reference)
#include <cuda_runtime.h>

#define BB   4
#define CC   256
#define HH   56
#define WWD  56
#define HWP  3136        // 56*56
#define CR   64
#define GG   16
#define KW   7
#define GK   784         // G*K*K
#define EPSV 1e-5f

// Scratch (no allocations allowed; static device global)
__device__ float g_w[(size_t)BB * GK * HWP];   // 39.3 MB

// ---- packed fp32 helpers (Blackwell f32x2) --------------------------------
__device__ __forceinline__ unsigned long long pk2(float lo, float hi) {
    unsigned long long r;
    asm("mov.b64 %0, {%1, %2};" : "=l"(r) : "f"(lo), "f"(hi));
    return r;
}
__device__ __forceinline__ void upk2(unsigned long long p, float& lo, float& hi) {
    asm("mov.b64 {%0, %1}, %2;" : "=f"(lo), "=f"(hi) : "l"(p));
}
__device__ __forceinline__ unsigned long long ffma2(
    unsigned long long a, unsigned long long b, unsigned long long c) {
    unsigned long long d;
    asm("fma.rn.f32x2 %0, %1, %2, %3;" : "=l"(d) : "l"(a), "l"(b), "l"(c));
    return d;
}

// ---------------------------------------------------------------------------
// Fused kernel-generation: t = relu(BN(W1@x+b1)) kept in smem, then
// w = W2@t + b2 streamed to g_w.  Block = 32 pixels, 128 threads.
// ---------------------------------------------------------------------------
__global__ __launch_bounds__(128) void gen_tw_kernel(
    const float* __restrict__ x,  const float* __restrict__ W1,
    const float* __restrict__ b1, const float* __restrict__ gamma,
    const float* __restrict__ beta, const float* __restrict__ mean,
    const float* __restrict__ var,  const float* __restrict__ W2,
    const float* __restrict__ b2)
{
    __shared__ float Ts[64][36];                  // t, [k=cr][px], resident
    __shared__ union {
        struct { float Xs[64][36]; float Ws[64][68]; } s1;   // stage-1 staging
        struct { float W2s[64][116]; } s2;                   // stage-2 staging
    } U;

    const int tid = threadIdx.x;
    const int m0  = blockIdx.x * 32;
    const int b   = m0 / HWP;
    const int p0  = m0 % HWP;         // 3136 % 32 == 0: never straddles batch
    const int pxg = tid & 7;          // 8 pixel-quads (4 px each)
    const int grp = tid >> 3;         // 0..15

    // ================= stage 1: 32px x 64out, K=256 =================
    unsigned long long acc1[4][2];    // [o][pxpair]
    const unsigned long long z2 = pk2(0.f, 0.f);
    #pragma unroll
    for (int j = 0; j < 4; j++) { acc1[j][0] = z2; acc1[j][1] = z2; }

    for (int c0 = 0; c0 < CC; c0 += 64) {
        // Xs[k][px]
        #pragma unroll
        for (int r = tid >> 5; r < 64; r += 4)
            U.s1.Xs[r][tid & 31] = x[((size_t)b * CC + c0 + r) * HWP + p0 + (tid & 31)];
        // Ws[k][o] = W1[o][c0+k], float4 on k
        {
            const int kq = tid & 15;
            #pragma unroll
            for (int o = tid >> 4; o < 64; o += 8) {
                float4 v = *(const float4*)&W1[o * CC + c0 + 4 * kq];
                U.s1.Ws[4 * kq + 0][o] = v.x;
                U.s1.Ws[4 * kq + 1][o] = v.y;
                U.s1.Ws[4 * kq + 2][o] = v.z;
                U.s1.Ws[4 * kq + 3][o] = v.w;
            }
        }
        __syncthreads();

        #pragma unroll 8
        for (int k = 0; k < 64; k++) {
            float4 a4 = *(const float4*)&U.s1.Xs[k][4 * pxg];
            float4 w4 = *(const float4*)&U.s1.Ws[k][4 * grp];
            unsigned long long a01 = pk2(a4.x, a4.y);
            unsigned long long a23 = pk2(a4.z, a4.w);
            float wj[4] = {w4.x, w4.y, w4.z, w4.w};
            #pragma unroll
            for (int j = 0; j < 4; j++) {
                unsigned long long wp = pk2(wj[j], wj[j]);
                acc1[j][0] = ffma2(a01, wp, acc1[j][0]);
                acc1[j][1] = ffma2(a23, wp, acc1[j][1]);
            }
        }
        __syncthreads();
    }

    // BN + ReLU epilogue -> Ts[o][px]
    #pragma unroll
    for (int j = 0; j < 4; j++) {
        const int o = 4 * grp + j;
        const float sc = gamma[o] * rsqrtf(var[o] + EPSV);
        const float sh = beta[o] - mean[o] * sc;
        const float bv = b1[o];
        float v0, v1, v2, v3;
        upk2(acc1[j][0], v0, v1);
        upk2(acc1[j][1], v2, v3);
        Ts[o][4 * pxg + 0] = fmaxf((v0 + bv) * sc + sh, 0.f);
        Ts[o][4 * pxg + 1] = fmaxf((v1 + bv) * sc + sh, 0.f);
        Ts[o][4 * pxg + 2] = fmaxf((v2 + bv) * sc + sh, 0.f);
        Ts[o][4 * pxg + 3] = fmaxf((v3 + bv) * sc + sh, 0.f);
    }

    // ================= stage 2: 32px x 784n, K=64 =================
    const int  ng     = grp;            // 0..15, only 0..13 active
    const bool active = (ng < 14);

    for (int n0 = 0; n0 < GK; n0 += 112) {
        // W2s[k][n] = W2[n0+n][k], float4 on k
        {
            const int kq = tid & 15;
            #pragma unroll
            for (int n = tid >> 4; n < 112; n += 8) {
                float4 v = *(const float4*)&W2[(n0 + n) * CR + 4 * kq];
                U.s2.W2s[4 * kq + 0][n] = v.x;
                U.s2.W2s[4 * kq + 1][n] = v.y;
                U.s2.W2s[4 * kq + 2][n] = v.z;
                U.s2.W2s[4 * kq + 3][n] = v.w;
            }
        }
        __syncthreads();

        if (active) {
            unsigned long long acc2[8][2];
            #pragma unroll
            for (int j = 0; j < 8; j++) { acc2[j][0] = z2; acc2[j][1] = z2; }

            #pragma unroll 8
            for (int k = 0; k < 64; k++) {
                float4 a4 = *(const float4*)&Ts[k][4 * pxg];
                unsigned long long a01 = pk2(a4.x, a4.y);
                unsigned long long a23 = pk2(a4.z, a4.w);
                float4 wA = *(const float4*)&U.s2.W2s[k][8 * ng];
                float4 wB = *(const float4*)&U.s2.W2s[k][8 * ng + 4];
                float wj[8] = {wA.x, wA.y, wA.z, wA.w, wB.x, wB.y, wB.z, wB.w};
                #pragma unroll
                for (int j = 0; j < 8; j++) {
                    unsigned long long wp = pk2(wj[j], wj[j]);
                    acc2[j][0] = ffma2(a01, wp, acc2[j][0]);
                    acc2[j][1] = ffma2(a23, wp, acc2[j][1]);
                }
            }

            #pragma unroll
            for (int j = 0; j < 8; j++) {
                const int n = n0 + 8 * ng + j;
                const float bv = b2[n];
                float v0, v1, v2, v3;
                upk2(acc2[j][0], v0, v1);
                upk2(acc2[j][1], v2, v3);
                float4 o4 = make_float4(v0 + bv, v1 + bv, v2 + bv, v3 + bv);
                *(float4*)&g_w[((size_t)b * GK + n) * HWP + p0 + 4 * pxg] = o4;
            }
        }
        __syncthreads();
    }
}

// ---------------------------------------------------------------------------
// Involution with channel-group reuse.
// Block = (h-strip of 4 rows, g, b); 224 threads = 4 ch-quads x 56 px-quads.
// w staged once in smem for all 16 channels; x halo staged in smem.
// ---------------------------------------------------------------------------
#define XS_CH_STRIDE 650          // 10 rows * 65 cols
#define XS_ELEMS     (16 * XS_CH_STRIDE)          // 10400
#define WS_ELEMS     (49 * 4 * 56)                // 10976
#define INV_SMEM_BYTES ((XS_ELEMS + WS_ELEMS) * 4)   // 85504 B

__global__ __launch_bounds__(224) void inv_kernel(
    const float* __restrict__ x, float* __restrict__ out)
{
    extern __shared__ float sm[];
    float* xs = sm;                 // [16 ch][10 rows][65 cols], row h0-3+rr, col -3+cc
    float* ws = sm + XS_ELEMS;      // [49 tap][4 rows][56 cols]

    const int tid = threadIdx.x;
    const int h0  = blockIdx.x * 4;
    const int g   = blockIdx.y;
    const int b   = blockIdx.z;

    // stage x halo
    const float* xg = x + ((size_t)b * CC + g * 16) * HWP;
    for (int idx = tid; idx < XS_ELEMS; idx += 224) {
        const int ch  = idx / XS_CH_STRIDE;
        const int rem = idx % XS_CH_STRIDE;
        const int rr  = rem / 65;
        const int cc  = rem % 65;
        const int hh  = h0 - 3 + rr;
        const int wc  = cc - 3;
        float v = 0.f;
        if (hh >= 0 && hh < HH && wc >= 0 && wc < WWD)
            v = xg[(size_t)ch * HWP + hh * WWD + wc];
        xs[idx] = v;
    }
    // stage w (4 rows x 56 cols per tap)
    const float* wg = g_w + ((size_t)b * GK + g * 49) * HWP + h0 * WWD;
    for (int idx = tid; idx < WS_ELEMS; idx += 224) {
        const int tap = idx / 224;
        const int rem = idx % 224;      // r*56 + col
        ws[idx] = wg[(size_t)tap * HWP + rem];
    }
    __syncthreads();

    const int cq   = tid & 3;           // channel quad
    const int pxq  = tid >> 2;          // 0..55
    const int r    = pxq / 14;          // row within strip
    const int col0 = 4 * (pxq % 14);    // pixel quad start
    const int ch0  = 4 * cq;

    float acc[4][4] = {};               // [ch][px]

    #pragma unroll
    for (int i = 0; i < KW; i++) {
        float xr[4][10];
        #pragma unroll
        for (int c = 0; c < 4; c++) {
            const float* xrow = xs + (ch0 + c) * XS_CH_STRIDE + (r + i) * 65 + col0;
            #pragma unroll
            for (int d = 0; d < 10; d++) xr[c][d] = xrow[d];
        }
        #pragma unroll
        for (int j = 0; j < KW; j++) {
            float4 wv = *(const float4*)&ws[(i * 7 + j) * 224 + r * 56 + col0];
            #pragma unroll
            for (int c = 0; c < 4; c++) {
                acc[c][0] = fmaf(xr[c][j + 0], wv.x, acc[c][0]);
                acc[c][1] = fmaf(xr[c][j + 1], wv.y, acc[c][1]);
                acc[c][2] = fmaf(xr[c][j + 2], wv.z, acc[c][2]);
                acc[c][3] = fmaf(xr[c][j + 3], wv.w, acc[c][3]);
            }
        }
    }

    #pragma unroll
    for (int c = 0; c < 4; c++) {
        float4 o4 = make_float4(acc[c][0], acc[c][1], acc[c][2], acc[c][3]);
        *(float4*)&out[((size_t)b * CC + g * 16 + ch0 + c) * HWP + (h0 + r) * WWD + col0] = o4;
    }
}

// ---------------------------------------------------------------------------
extern "C" void kernel_launch(void* const* d_in, const int* in_sizes, int n_in,
                              void* d_out, int out_size)
{
    const float* x     = (const float*)d_in[0];
    const float* W1    = (const float*)d_in[1];
    const float* b1    = (const float*)d_in[2];
    const float* gamma = (const float*)d_in[3];
    const float* beta  = (const float*)d_in[4];
    const float* mean  = (const float*)d_in[5];
    const float* var   = (const float*)d_in[6];
    const float* W2    = (const float*)d_in[7];
    const float* b2    = (const float*)d_in[8];
    float* out = (float*)d_out;

    static int smem_set = 0;
    if (!smem_set) {
        cudaFuncSetAttribute(inv_kernel,
                             cudaFuncAttributeMaxDynamicSharedMemorySize,
                             INV_SMEM_BYTES);
        smem_set = 1;
    }

    gen_tw_kernel<<<392, 128>>>(x, W1, b1, gamma, beta, mean, var, W2, b2);
    inv_kernel<<<dim3(14, GG, BB), 224, INV_SMEM_BYTES>>>(x, out);
}